// round 13
// baseline (speedup 1.0000x reference)
#include <cuda_runtime.h>
#include <math.h>

#define NN 65536
#define EE 1048576
#define BB 256

typedef unsigned long long ull;

// ---------------- device scratch (static globals; no allocation) ----------------
__device__ __align__(16) float g_h[NN * 64];      // node state h
__device__ __align__(16) float g_hB[NN * 64];     // ping-pong buffer
__device__ __align__(16) float g_agg[NN * 64];    // gathered sum of h[src] (step 1)
__device__ __align__(16) float g_aggx[NN * 32];   // gathered sum of x[src] (step 0)
__device__ __align__(16) float g_gix[NN * 192];   // W_ih[:,64:96]@x + b_ih
__device__ __align__(16) float g_Wx2[256 * 32];   // [o][k] o<64: W_mlp ; o>=64: W_ih x-part
__device__ float g_bx[256];
// GRU weights, [k][192] layout for coalesced smem staging
__device__ __align__(16) float g_WgA[64 * 192];   // Wcomb = W_ih_m @ W_conv (r,z,n)
__device__ __align__(16) float g_WgAX[32 * 192];  // Wcomb @ W_mlp  (step-0 x-space)
__device__ __align__(16) float g_WgH[64 * 192];   // W_hh (r,z,n)
__device__ float g_bvec[192];                     // W_ih_m @ b_conv
__device__ float g_bvec0[192];                    // Wcomb@b_mlp + W_ih_m@b_conv
// transposed Set2Set/head weights (coalesced: k-major)
__device__ __align__(16) float g_lWihT[128 * 256];
__device__ __align__(16) float g_lWhhT[64 * 256];
__device__ __align__(16) float g_W1T[128 * 64];
// CSR
__device__ int g_cnt[NN];
__device__ int g_off[NN];
__device__ int g_cur[NN];
__device__ float g_degf[NN];
__device__ int g_bsum[256];
__device__ int g_bpre[256];
__device__ int g_csr[EE];
// batch / graph ranges
__device__ int g_bhist[256];
__device__ int g_gbeg[257];
__device__ int g_is64e, g_is64b;

__device__ __forceinline__ float sigm(float x) { return 1.0f / (1.0f + expf(-x)); }

// packed fp32x2 fma (sm_103a)
__device__ __forceinline__ void ffma2(ull& d, ull a, ull b) {
    asm("fma.rn.f32x2 %0, %1, %2, %3;" : "=l"(d) : "l"(a), "l"(b), "l"(d));
}
__device__ __forceinline__ ull packdup(float x) {
    ull r;
    asm("mov.b64 %0, {%1, %1};" : "=l"(r) : "f"(x));
    return r;
}
__device__ __forceinline__ float lo2(ull v) { return __uint_as_float((unsigned)(v & 0xffffffffull)); }
__device__ __forceinline__ float hi2(ull v) { return __uint_as_float((unsigned)(v >> 32)); }

__device__ __forceinline__ int ld_idx(const int* p, int i, int is64) {
    return is64 ? p[2 * i] : p[i];
}

// ---------------- fused prep: dtype detect + all weight re-layouts + zeroing ----------------
__global__ void k_prepB(const float* W_mlp, const float* b_mlp,
                        const float* W_ih, const float* b_ih,
                        const float* W_hh, const float* W_conv, const float* b_conv,
                        const float* lWih, const float* lWhh, const float* W1,
                        const int* ei, const int* bt) {
    if (blockIdx.x == 0 && threadIdx.x < 32) {
        int lane = threadIdx.x;
        int v  = ei[2 * EE - 1 - 2 * lane];
        int vb = bt[NN - 1 - 2 * lane];
        unsigned m  = __ballot_sync(0xffffffffu, v != 0);
        unsigned mb = __ballot_sync(0xffffffffu, vb != 0);
        if (lane == 0) { g_is64e = (m == 0u) ? 1 : 0; g_is64b = (mb == 0u) ? 1 : 0; }
    }
    int t = blockIdx.x * blockDim.x + threadIdx.x;
    if (t < 8192) {
        int o = t >> 5, k = t & 31;
        g_Wx2[t] = (o < 64) ? W_mlp[o * 32 + k] : W_ih[(o - 64) * 96 + 64 + k];
    } else if (t < 8448) {
        int o = t - 8192;
        g_bx[o] = (o < 64) ? b_mlp[o] : b_ih[o - 64];
    } else if (t < 20736) {
        int u = t - 8448;
        int g = u >> 12, j = (u >> 6) & 63, k = u & 63;
        const float* wr = W_ih + (g * 64 + j) * 96;
        float v = 0.f;
#pragma unroll 8
        for (int o = 0; o < 64; o++) v += wr[o] * W_conv[o * 64 + k];
        g_WgA[k * 192 + g * 64 + j] = v;
    } else if (t < 33024) {
        int u = t - 20736;
        int g = u >> 12, j = (u >> 6) & 63, k = u & 63;
        g_WgH[k * 192 + g * 64 + j] = W_hh[(g * 64 + j) * 64 + k];
    } else if (t < 33216) {
        int o = t - 33024;
        const float* wr = W_ih + o * 96;
        float v = 0.f;
#pragma unroll 8
        for (int o2 = 0; o2 < 64; o2++) v += wr[o2] * b_conv[o2];
        g_bvec[o] = v;
    } else if (t < 49600) {
        ((int4*)g_cnt)[t - 33216] = make_int4(0, 0, 0, 0);
    } else if (t < 49856) {
        g_bhist[t - 49600] = 0;
    } else if (t < 82624) {
        int u = t - 49856;
        int k = u >> 8, o = u & 255;
        g_lWihT[k * 256 + o] = lWih[o * 128 + k];
    } else if (t < 99008) {
        int u = t - 82624;
        int k = u >> 8, o = u & 255;
        g_lWhhT[k * 256 + o] = lWhh[o * 64 + k];
    } else if (t < 107200) {
        int u = t - 99008;
        int k = u >> 6, o = u & 63;
        g_W1T[k * 64 + o] = W1[o * 128 + k];
    } else if (t < 113344) {
        // WgAX[kp][o] = sum_{o2,k} W_ih[o*96+o2] W_conv[o2*64+k] W_mlp[k*32+kp]
        int u = t - 107200;
        int kp = u / 192, o = u % 192;
        const float* wr = W_ih + o * 96;
        float acc = 0.f;
        for (int o2 = 0; o2 < 64; o2++) {
            const float* wc = W_conv + o2 * 64;
            float s0 = 0.f, s1 = 0.f, s2 = 0.f, s3 = 0.f;
#pragma unroll 4
            for (int k = 0; k < 64; k += 4) {
                s0 += wc[k]     * W_mlp[k * 32 + kp];
                s1 += wc[k + 1] * W_mlp[(k + 1) * 32 + kp];
                s2 += wc[k + 2] * W_mlp[(k + 2) * 32 + kp];
                s3 += wc[k + 3] * W_mlp[(k + 3) * 32 + kp];
            }
            acc += wr[o2] * ((s0 + s1) + (s2 + s3));
        }
        g_WgAX[kp * 192 + o] = acc;
    } else if (t < 113536) {
        // bvec0[o] = sum_o2 W_ih[o*96+o2] * (b_conv[o2] + W_conv[o2]@b_mlp)
        int o = t - 113344;
        const float* wr = W_ih + o * 96;
        float acc = 0.f;
        for (int o2 = 0; o2 < 64; o2++) {
            const float* wc = W_conv + o2 * 64;
            float s0 = 0.f, s1 = 0.f, s2 = 0.f, s3 = 0.f;
#pragma unroll 4
            for (int k = 0; k < 64; k += 4) {
                s0 += wc[k] * b_mlp[k];
                s1 += wc[k + 1] * b_mlp[k + 1];
                s2 += wc[k + 2] * b_mlp[k + 2];
                s3 += wc[k + 3] * b_mlp[k + 3];
            }
            acc += wr[o2] * (b_conv[o2] + ((s0 + s1) + (s2 + s3)));
        }
        g_bvec0[o] = acc;
    }
}

// ---------------- histograms ----------------
__global__ void k_hist(const int* ei, const int* bt) {
    int t = blockIdx.x * 256 + threadIdx.x;
    int dst = ld_idx(ei, EE + t, g_is64e);
    atomicAdd(&g_cnt[dst], 1);
    if (t < NN) {
        int b = ld_idx(bt, t, g_is64b);
        atomicAdd(&g_bhist[b], 1);
    }
}
__global__ void k_scan1() {
    __shared__ int s[256];
    int tid = threadIdx.x;
    int i = blockIdx.x * 256 + tid;
    int v = g_cnt[i];
    s[tid] = v; __syncthreads();
    for (int d = 1; d < 256; d <<= 1) {
        int t = (tid >= d) ? s[tid - d] : 0; __syncthreads();
        s[tid] += t; __syncthreads();
    }
    g_off[i] = s[tid] - v;
    if (tid == 255) g_bsum[blockIdx.x] = s[255];
}
__global__ void k_scan2() {
    __shared__ int s[256];
    int tid = threadIdx.x;
    int v = g_bsum[tid];
    s[tid] = v; __syncthreads();
    for (int d = 1; d < 256; d <<= 1) {
        int t = (tid >= d) ? s[tid - d] : 0; __syncthreads();
        s[tid] += t; __syncthreads();
    }
    g_bpre[tid] = s[tid] - v;
    __syncthreads();
    int vb = g_bhist[tid];
    s[tid] = vb; __syncthreads();
    for (int d = 1; d < 256; d <<= 1) {
        int t = (tid >= d) ? s[tid - d] : 0; __syncthreads();
        s[tid] += t; __syncthreads();
    }
    g_gbeg[tid] = s[tid] - vb;
    if (tid == 255) g_gbeg[256] = s[255];
}
__global__ void k_scan3() {
    int i = blockIdx.x * 256 + threadIdx.x;
    int off = g_off[i] + g_bpre[blockIdx.x];
    g_off[i] = off;
    g_cur[i] = off;
    g_degf[i] = (float)g_cnt[i];
}
__global__ void k_fill(const int* ei) {
    int e = blockIdx.x * 256 + threadIdx.x;
    int is64 = g_is64e;
    int src = ld_idx(ei, e, is64);
    int dst = ld_idx(ei, EE + e, is64);
    int p = atomicAdd(&g_cur[dst], 1);
    g_csr[p] = src;
}

// ---------------- node MLP + gix precompute: [N,32]@[32,256] ----------------
__global__ __launch_bounds__(256) void k_mlp2(const float* x) {
    int o = threadIdx.x;
    int nb = blockIdx.x * 16;
    const ulonglong2* Wp = (const ulonglong2*)(g_Wx2 + o * 32);
    ulonglong2 w[8];
#pragma unroll
    for (int kk = 0; kk < 8; kk++) w[kk] = __ldg(&Wp[kk]);
    float bias = g_bx[o];
#pragma unroll 2
    for (int i = 0; i < 16; i++) {
        int n = nb + i;
        const ulonglong2* xr = (const ulonglong2*)(x + (size_t)n * 32);
        ull a0 = 0ull, a1 = 0ull;
#pragma unroll
        for (int kk = 0; kk < 8; kk++) {
            ulonglong2 v = __ldg(&xr[kk]);
            ffma2(a0, v.x, w[kk].x);
            ffma2(a1, v.y, w[kk].y);
        }
        float v = lo2(a0) + hi2(a0) + lo2(a1) + hi2(a1) + bias;
        if (o < 64) g_h[(size_t)n * 64 + o] = v;
        else        g_gix[(size_t)n * 192 + (o - 64)] = v;
    }
}

// ---------------- step-0 gather on x: aggx[n] = sum_{e: dst=n} x[src] ----------------
__global__ __launch_bounds__(256) void k_gatherx(const float* x) {
    int warp = threadIdx.x >> 5, lane = threadIdx.x & 31;
    int node = blockIdx.x * 8 + warp;
    int beg = g_off[node], cnt = g_cnt[node];
    float a = 0.f;
    int t = 0;
    for (; t + 4 <= cnt; t += 4) {
        int s0 = __ldg(&g_csr[beg + t]);
        int s1 = __ldg(&g_csr[beg + t + 1]);
        int s2 = __ldg(&g_csr[beg + t + 2]);
        int s3 = __ldg(&g_csr[beg + t + 3]);
        a += __ldg(&x[(size_t)s0 * 32 + lane]) + __ldg(&x[(size_t)s1 * 32 + lane]) +
             __ldg(&x[(size_t)s2 * 32 + lane]) + __ldg(&x[(size_t)s3 * 32 + lane]);
    }
    for (; t < cnt; t++) {
        int s = __ldg(&g_csr[beg + t]);
        a += __ldg(&x[(size_t)s * 32 + lane]);
    }
    g_aggx[(size_t)node * 32 + lane] = a;
}

// ---------------- step-1 gather on h: agg[n] = sum_{e: dst=n} hB[src] ----------------
__global__ __launch_bounds__(256) void k_gather() {
    const float* hsrc = g_hB;
    int warp = threadIdx.x >> 5, lane = threadIdx.x & 31;
    int node = blockIdx.x * 8 + warp;
    int beg = g_off[node], cnt = g_cnt[node];
    const float2* hb = (const float2*)hsrc;
    float ax = 0.f, ay = 0.f;
    int t = 0;
    for (; t + 4 <= cnt; t += 4) {
        int s0 = __ldg(&g_csr[beg + t]);
        int s1 = __ldg(&g_csr[beg + t + 1]);
        int s2 = __ldg(&g_csr[beg + t + 2]);
        int s3 = __ldg(&g_csr[beg + t + 3]);
        float2 v0 = __ldg(&hb[(size_t)s0 * 32 + lane]);
        float2 v1 = __ldg(&hb[(size_t)s1 * 32 + lane]);
        float2 v2 = __ldg(&hb[(size_t)s2 * 32 + lane]);
        float2 v3 = __ldg(&hb[(size_t)s3 * 32 + lane]);
        ax += v0.x + v1.x + v2.x + v3.x;
        ay += v0.y + v1.y + v2.y + v3.y;
    }
    for (; t < cnt; t++) {
        int s = __ldg(&g_csr[beg + t]);
        float2 v = __ldg(&hb[(size_t)s * 32 + lane]);
        ax += v.x; ay += v.y;
    }
    float2 out; out.x = ax; out.y = ay;
    ((float2*)g_agg)[(size_t)node * 32 + lane] = out;
}

// ---------------- GRU phase helper ----------------
template<int K, int STR>
__device__ __forceinline__ void gphase(const float* Ws, const float* xrow, int tg, ull acc[3][8]) {
#pragma unroll 4
    for (int k = 0; k < K; k++) {
        ull w0 = *(const ull*)&Ws[k * 192 + tg * 2];
        ull w1 = *(const ull*)&Ws[k * 192 + 64 + tg * 2];
        ull w2 = *(const ull*)&Ws[k * 192 + 128 + tg * 2];
#pragma unroll
        for (int n = 0; n < 8; n++) {
            ull xd = packdup(xrow[n * STR + k]);
            ffma2(acc[0][n], xd, w0);
            ffma2(acc[1][n], xd, w1);
            ffma2(acc[2][n], xd, w2);
        }
    }
}

// ---------------- fused GRU step (conv-fused, both weight sets resident) ----------------
// step 0: phase1 = WgAX[32x192] @ aggx (x-space) ; step 1: WgA[64x192] @ agg
#define GRU_SMEM ((64 * 68 * 2 + 2 * 64 * 192) * 4)
__global__ __launch_bounds__(256) void k_gru3(int step, const float* b_hh) {
    const float* hin = step ? g_hB : g_h;
    float* hout      = step ? g_h  : g_hB;
    extern __shared__ float sm[];
    float* Xa  = sm;                  // [64][68] (step1) or [64][36] (step0)
    float* Xh  = Xa + 64 * 68;        // [64][68]
    float* WsA = Xh + 64 * 68;        // up to 64*192
    float* WsH = WsA + 64 * 192;      // 64*192

    int tid = threadIdx.x;
    int nb = blockIdx.x * 64;

    for (int i = tid; i < 64 * 16; i += 256) {
        int n = i >> 4, kq = i & 15;
        *(float4*)&Xh[n * 68 + kq * 4] = *(const float4*)&hin[(size_t)(nb + n) * 64 + kq * 4];
    }
    if (step) {
        for (int i = tid; i < 64 * 16; i += 256) {
            int n = i >> 4, kq = i & 15;
            *(float4*)&Xa[n * 68 + kq * 4] = *(const float4*)&g_agg[(size_t)(nb + n) * 64 + kq * 4];
        }
        for (int i = tid; i < 64 * 192 / 4; i += 256)
            ((float4*)WsA)[i] = ((const float4*)g_WgA)[i];
    } else {
        for (int i = tid; i < 64 * 8; i += 256) {
            int n = i >> 3, kq = i & 7;
            *(float4*)&Xa[n * 36 + kq * 4] = *(const float4*)&g_aggx[(size_t)(nb + n) * 32 + kq * 4];
        }
        for (int i = tid; i < 32 * 192 / 4; i += 256)
            ((float4*)WsA)[i] = ((const float4*)g_WgAX)[i];
    }
    for (int i = tid; i < 64 * 192 / 4; i += 256)
        ((float4*)WsH)[i] = ((const float4*)g_WgH)[i];
    __syncthreads();

    int tg = tid & 31;
    int tn = tid >> 5;
    const float* xh = Xh + (tn * 8) * 68;

    ull gia[3][8], gha[3][8];
#pragma unroll
    for (int g = 0; g < 3; g++)
#pragma unroll
        for (int n = 0; n < 8; n++) { gia[g][n] = 0ull; gha[g][n] = 0ull; }

    if (step) gphase<64, 68>(WsA, Xa + (tn * 8) * 68, tg, gia);
    else      gphase<32, 36>(WsA, Xa + (tn * 8) * 36, tg, gia);
    gphase<64, 68>(WsH, xh, tg, gha);

    const float* bv = step ? g_bvec : g_bvec0;
    int j0 = tg * 2;
    float2 bh_r = *(const float2*)&b_hh[j0];
    float2 bh_z = *(const float2*)&b_hh[64 + j0];
    float2 bh_n = *(const float2*)&b_hh[128 + j0];
    float2 bv_r = *(const float2*)&bv[j0];
    float2 bv_z = *(const float2*)&bv[64 + j0];
    float2 bv_n = *(const float2*)&bv[128 + j0];
#pragma unroll
    for (int n = 0; n < 8; n++) {
        int node = nb + tn * 8 + n;
        float degf = g_degf[node];
        const float* gx = g_gix + (size_t)node * 192;
        float2 gx_r = *(const float2*)&gx[j0];
        float2 gx_z = *(const float2*)&gx[64 + j0];
        float2 gx_n = *(const float2*)&gx[128 + j0];

        float gir0 = lo2(gia[0][n]) + gx_r.x + degf * bv_r.x;
        float gir1 = hi2(gia[0][n]) + gx_r.y + degf * bv_r.y;
        float giz0 = lo2(gia[1][n]) + gx_z.x + degf * bv_z.x;
        float giz1 = hi2(gia[1][n]) + gx_z.y + degf * bv_z.y;
        float gin0 = lo2(gia[2][n]) + gx_n.x + degf * bv_n.x;
        float gin1 = hi2(gia[2][n]) + gx_n.y + degf * bv_n.y;
        float ghr0 = lo2(gha[0][n]) + bh_r.x;
        float ghr1 = hi2(gha[0][n]) + bh_r.y;
        float ghz0 = lo2(gha[1][n]) + bh_z.x;
        float ghz1 = hi2(gha[1][n]) + bh_z.y;
        float ghn0 = lo2(gha[2][n]) + bh_n.x;
        float ghn1 = hi2(gha[2][n]) + bh_n.y;

        float r0 = sigm(gir0 + ghr0), r1 = sigm(gir1 + ghr1);
        float z0 = sigm(giz0 + ghz0), z1 = sigm(giz1 + ghz1);
        float ng0 = tanhf(gin0 + r0 * ghn0), ng1 = tanhf(gin1 + r1 * ghn1);
        float h0 = xh[n * 68 + j0], h1 = xh[n * 68 + j0 + 1];
        float2 o;
        o.x = (1.f - z0) * ng0 + z0 * h0;
        o.y = (1.f - z1) * ng1 + z1 * h1;
        *(float2*)&hout[(size_t)node * 64 + j0] = o;
    }
}

// ---------------- fused Set2Set (3 iters) + head: one block per graph, 512 threads ----------------
__global__ __launch_bounds__(512) void k_s2s(const float* lbih, const float* lbhh,
                                             const float* b1, const float* W2,
                                             const float* b2, float* out) {
    int g = blockIdx.x, tid = threadIdx.x;
    int warp = tid >> 5, lane = tid & 31;      // 16 warps
    __shared__ float qs[64], cs[64], qstar[128], gates[256];
    __shared__ float redm[16], reda[16], rsum[16][64];
    __shared__ float hid[64], lg[4];
    int s = g_gbeg[g], e = g_gbeg[g + 1];
    if (tid < 64) { qs[tid] = 0.f; cs[tid] = 0.f; }
    if (tid < 128) qstar[tid] = 0.f;
    __syncthreads();

    for (int it = 0; it < 3; it++) {
        if (tid < 256) {
            float acc = lbih[tid] + lbhh[tid];
#pragma unroll 8
            for (int k = 0; k < 128; k++) acc += g_lWihT[k * 256 + tid] * qstar[k];
#pragma unroll 8
            for (int k = 0; k < 64; k++) acc += g_lWhhT[k * 256 + tid] * qs[k];
            gates[tid] = acc;
        }
        __syncthreads();
        if (tid < 64) {
            float i = sigm(gates[tid]);
            float f = sigm(gates[64 + tid]);
            float gg = tanhf(gates[128 + tid]);
            float o = sigm(gates[192 + tid]);
            float c = f * cs[tid] + i * gg;
            cs[tid] = c;
            qs[tid] = o * tanhf(c);
        }
        __syncthreads();

        float q0 = qs[lane * 2], q1 = qs[lane * 2 + 1];
        // pass 1: segment max of e = <h_n, q> ; 16 warps, x2 unroll
        float mymax = -1e30f;
        for (int n = s + warp; n < e; n += 32) {
            int n2 = n + 16;
            float2 hv = __ldg(&((const float2*)g_h)[(size_t)n * 32 + lane]);
            float p = hv.x * q0 + hv.y * q1;
            float p2 = 0.f;
            if (n2 < e) {
                float2 hv2 = __ldg(&((const float2*)g_h)[(size_t)n2 * 32 + lane]);
                p2 = hv2.x * q0 + hv2.y * q1;
            }
#pragma unroll
            for (int d = 16; d >= 1; d >>= 1) {
                p  += __shfl_xor_sync(0xffffffffu, p, d);
                p2 += __shfl_xor_sync(0xffffffffu, p2, d);
            }
            mymax = fmaxf(mymax, p);
            if (n2 < e) mymax = fmaxf(mymax, p2);
        }
        if (lane == 0) redm[warp] = mymax;
        __syncthreads();
        float em = redm[0];
#pragma unroll
        for (int w = 1; w < 16; w++) em = fmaxf(em, redm[w]);
        // pass 2: a = exp(e - em); asum; r = sum a*h (recompute e; x2 unroll)
        float r0 = 0.f, r1 = 0.f, mysum = 0.f;
        for (int n = s + warp; n < e; n += 32) {
            int n2 = n + 16;
            float2 hv = __ldg(&((const float2*)g_h)[(size_t)n * 32 + lane]);
            float p = hv.x * q0 + hv.y * q1;
            float p2 = 0.f;
            float2 hv2 = make_float2(0.f, 0.f);
            if (n2 < e) {
                hv2 = __ldg(&((const float2*)g_h)[(size_t)n2 * 32 + lane]);
                p2 = hv2.x * q0 + hv2.y * q1;
            }
#pragma unroll
            for (int d = 16; d >= 1; d >>= 1) {
                p  += __shfl_xor_sync(0xffffffffu, p, d);
                p2 += __shfl_xor_sync(0xffffffffu, p2, d);
            }
            float a = expf(p - em);
            mysum += a; r0 += a * hv.x; r1 += a * hv.y;
            if (n2 < e) {
                float a2 = expf(p2 - em);
                mysum += a2; r0 += a2 * hv2.x; r1 += a2 * hv2.y;
            }
        }
        if (lane == 0) reda[warp] = mysum;
        rsum[warp][lane * 2] = r0;
        rsum[warp][lane * 2 + 1] = r1;
        __syncthreads();
        float asum = 0.f;
#pragma unroll
        for (int w = 0; w < 16; w++) asum += reda[w];
        asum = fmaxf(asum, 1e-16f);
        if (tid < 64) {
            float rr = 0.f;
#pragma unroll
            for (int w = 0; w < 16; w++) rr += rsum[w][tid];
            qstar[64 + tid] = rr / asum;
            qstar[tid] = qs[tid];
        }
        __syncthreads();
    }

    if (tid < 64) {
        float acc = b1[tid];
#pragma unroll 8
        for (int k = 0; k < 128; k++) acc += g_W1T[k * 64 + tid] * qstar[k];
        hid[tid] = fmaxf(acc, 0.f);
    }
    __syncthreads();
    if (tid < 4) {
        float a = b2[tid];
        const float* w2 = W2 + tid * 64;
#pragma unroll 8
        for (int k = 0; k < 64; k++) a += w2[k] * hid[k];
        lg[tid] = a;
    }
    __syncthreads();
    if (tid < 4) {
        float m = fmaxf(fmaxf(lg[0], lg[1]), fmaxf(lg[2], lg[3]));
        float sum = expf(lg[0] - m) + expf(lg[1] - m) + expf(lg[2] - m) + expf(lg[3] - m);
        out[g * 4 + tid] = lg[tid] - m - logf(sum);
    }
}

// ---------------- launch ----------------
extern "C" void kernel_launch(void* const* d_in, const int* in_sizes, int n_in,
                              void* d_out, int out_size) {
    const float* x       = (const float*)d_in[0];
    const int*   ei      = (const int*)d_in[1];
    const int*   bt      = (const int*)d_in[2];
    const float* W_mlp   = (const float*)d_in[3];
    const float* b_mlp   = (const float*)d_in[4];
    const float* W_conv  = (const float*)d_in[5];
    const float* b_conv  = (const float*)d_in[6];
    const float* gWih    = (const float*)d_in[7];
    const float* gWhh    = (const float*)d_in[8];
    const float* gbih    = (const float*)d_in[9];
    const float* gbhh    = (const float*)d_in[10];
    const float* lWih    = (const float*)d_in[11];
    const float* lWhh    = (const float*)d_in[12];
    const float* lbih    = (const float*)d_in[13];
    const float* lbhh    = (const float*)d_in[14];
    const float* W1      = (const float*)d_in[15];
    const float* b1      = (const float*)d_in[16];
    const float* W2      = (const float*)d_in[17];
    const float* b2      = (const float*)d_in[18];
    float* out = (float*)d_out;

    static cudaStream_t sB = nullptr;
    static cudaEvent_t evA = nullptr, evB = nullptr;
    static bool init_done = false;
    if (!init_done) {
        cudaFuncSetAttribute(k_gru3, cudaFuncAttributeMaxDynamicSharedMemorySize, GRU_SMEM);
        cudaStreamCreateWithFlags(&sB, cudaStreamNonBlocking);
        cudaEventCreateWithFlags(&evA, cudaEventDisableTiming);
        cudaEventCreateWithFlags(&evB, cudaEventDisableTiming);
        init_done = true;
    }

    k_prepB<<<444, 256>>>(W_mlp, b_mlp, gWih, gbih, gWhh, W_conv, b_conv, lWih, lWhh, W1, ei, bt);

    // fork: CSR chain + x-gather on side stream; node MLP on main stream
    cudaEventRecord(evA, 0);
    cudaStreamWaitEvent(sB, evA, 0);
    k_hist<<<EE / 256, 256, 0, sB>>>(ei, bt);
    k_scan1<<<256, 256, 0, sB>>>();
    k_scan2<<<1, 256, 0, sB>>>();
    k_scan3<<<256, 256, 0, sB>>>();
    k_fill<<<EE / 256, 256, 0, sB>>>(ei);
    k_gatherx<<<NN / 8, 256, 0, sB>>>(x);
    cudaEventRecord(evB, sB);

    k_mlp2<<<NN / 16, 256>>>(x);

    cudaStreamWaitEvent(0, evB, 0);

    k_gru3<<<NN / 64, 256, GRU_SMEM>>>(0, gbhh);    // aggx -> g_hB
    k_gather<<<NN / 8, 256>>>();                    // g_hB -> g_agg
    k_gru3<<<NN / 64, 256, GRU_SMEM>>>(1, gbhh);    // -> g_h

    k_s2s<<<BB, 512>>>(lbih, lbhh, b1, W2, b2, out);
}